// round 14
// baseline (speedup 1.0000x reference)
#include <cuda_runtime.h>
#include <cuda_fp16.h>
#include <cstdint>

#define H 1024
#define C 56
#define T 64
#define NBLK 148
#define NT 1024

// ---------------- persistent global state (activations only) ----------------
__device__ __align__(16) float g_s1[H], g_s2[H], g_s3[H], g_BU1[H], g_BU2[H];
__device__ __align__(16) float g_TD1[H];
__device__ __align__(16) float g_r1[64], g_r2[H], g_r3[H];

// ---------------- striped monotonic-counter grid barrier ----------------
// R13 used ONE counter line for 148 release-REDs + all poll loads -> LTS
// per-address serialization put ~0.3-0.8us of queueing on every barrier.
// R14: 8 counters at 256B stride (distinct L2 slices). CTA c REDs slot c&7
// (<=19 REDs/line); warps 0-7 poll one slot each against per-slot targets
// (slots 0-3 own 19 CTAs, 4-7 own 18), then join at __syncthreads.
#define NSLOT 8
__device__ unsigned g_slots[NSLOT * 64];   // 256B stride
__device__ unsigned g_sbase[NSLOT];        // per-slot base (prev launches)

#define NBAR_TOTAL (1 + 3 * T)

__device__ __forceinline__ float tanhx(float x) {
    float y;
    asm("tanh.approx.f32 %0, %1;" : "=f"(y) : "f"(x));
    return y;
}
__device__ __forceinline__ float gatefn(float zi, float zg, float zo) {
    float si = fmaf(0.5f, tanhx(0.5f * zi), 0.5f);
    float so = fmaf(0.5f, tanhx(0.5f * zo), 0.5f);
    return so * tanhx(si * tanhx(zg));
}

__device__ __forceinline__ float wred(float v) {
#pragma unroll
    for (int o = 16; o; o >>= 1) v += __shfl_xor_sync(0xffffffffu, v, o);
    return v;
}

// lane-partial dot: 1024 fp16 weights (smem) x 1024 fp16 acts (smem), fp32 accum
__device__ __forceinline__ float dotph(const __half* __restrict__ ws,
                                       const __half* __restrict__ as, int lane) {
    float acc = 0.f;
    int o = lane << 3;
#pragma unroll
    for (int it = 0; it < 4; ++it, o += 256) {
        uint4 u = *reinterpret_cast<const uint4*>(ws + o);
        uint4 a = *reinterpret_cast<const uint4*>(as + o);
        float2 w0 = __half22float2(*(__half2*)&u.x), b0 = __half22float2(*(__half2*)&a.x);
        float2 w1 = __half22float2(*(__half2*)&u.y), b1 = __half22float2(*(__half2*)&a.y);
        float2 w2 = __half22float2(*(__half2*)&u.z), b2 = __half22float2(*(__half2*)&a.z);
        float2 w3 = __half22float2(*(__half2*)&u.w), b3 = __half22float2(*(__half2*)&a.w);
        acc += w0.x * b0.x + w0.y * b0.y + w1.x * b1.x + w1.y * b1.y
             + w2.x * b2.x + w2.y * b2.y + w3.x * b3.x + w3.y * b3.y;
    }
    return acc;
}

// lane-partial dot: 1024 fp32 weights (GLOBAL via __ldcg) x 1024 fp16 acts (smem)
__device__ __forceinline__ float dotgh(const float* __restrict__ wg,
                                       const __half* __restrict__ as, int lane) {
    float acc = 0.f;
    int o = lane << 3;
#pragma unroll
    for (int it = 0; it < 4; ++it, o += 256) {
        float4 w0 = __ldcg(reinterpret_cast<const float4*>(wg + o));
        float4 w1 = __ldcg(reinterpret_cast<const float4*>(wg + o + 4));
        uint4 a = *reinterpret_cast<const uint4*>(as + o);
        float2 b0 = __half22float2(*(__half2*)&a.x);
        float2 b1 = __half22float2(*(__half2*)&a.y);
        float2 b2 = __half22float2(*(__half2*)&a.z);
        float2 b3 = __half22float2(*(__half2*)&a.w);
        acc += w0.x * b0.x + w0.y * b0.y + w0.z * b1.x + w0.w * b1.y
             + w1.x * b2.x + w1.y * b2.y + w1.z * b3.x + w1.w * b3.y;
    }
    return acc;
}

#define BAR_ARRIVE()                                                        \
    do {                                                                    \
        ++nbar;                                                             \
        if (tid == 0)                                                       \
            asm volatile("red.release.gpu.global.add.u32 [%0], %1;"         \
                         :: "l"(g_slots + ((cta & 7) * 64)), "r"(1u)        \
                         : "memory");                                       \
    } while (0)

#define BAR_WAIT()                                                          \
    do {                                                                    \
        if (w < 8 && lane == 0) {                                           \
            unsigned tgt = sbase_r + nbar * ns_r;                           \
            unsigned v;                                                     \
            do {                                                            \
                asm volatile("ld.acquire.gpu.global.u32 %0, [%1];"          \
                             : "=r"(v) : "l"(g_slots + (w * 64)) : "memory"); \
            } while ((int)(v - tgt) < 0);                                   \
        }                                                                   \
        __syncthreads();                                                    \
    } while (0)

// ---------------- smem layout (bytes) — weights RESIDENT ----------------
#define OFF_W1TD 0         // Wih1 TD half, 21 rows x 2048B fp16
#define OFF_W2TD 43008     // Wih2 TD half, 21 rows
#define OFF_W2S  86016     // Wih2 BU half, 21 rows
#define OFF_W3   129024    // Wih3, 21 rows
#define OFF_PW1  172032    // W1, 7 rows
#define OFF_PW2  186368    // W2, 7 rows
#define OFF_PM1  200704    // M1 = Wih1_bu @ W0, 21 rows x 64 fp32
#define OFF_ACTA 206080    // fp16 act buffers, 2048B each
#define OFF_ACTB 208128
#define OFF_ACTC 210176
#define OFF_ACTD 212224
#define OFF_N0   214272    // fp32, 256B
#define OFF_GBUF 214528
#define OFF_ZP2  214656
#define OFF_CB1  214784
#define OFF_PV3  214912    // V3, 7 rows x 2048B fp16 (NEW: r3 dot goes LDS)
#define SMEM_BYTES 229248
// phase-0 W0 fp16 scratch (114,688 B at offset 0) overlaps the weight region;
// consumed (-> M1) before the weights are filled.

__global__ void __launch_bounds__(NT, 1) predcells_kernel(
    const float* __restrict__ x,
    const float* __restrict__ W0w, const float* __restrict__ W0b,
    const float* __restrict__ W1w, const float* __restrict__ W1b,
    const float* __restrict__ W2w, const float* __restrict__ W2b,
    const float* __restrict__ Wih1, const float* __restrict__ b1,
    const float* __restrict__ Wih2, const float* __restrict__ b2,
    const float* __restrict__ Wih3, const float* __restrict__ b3,
    const float* __restrict__ V1w, const float* __restrict__ V1b,
    const float* __restrict__ V2w, const float* __restrict__ V2b,
    const float* __restrict__ V3w, const float* __restrict__ V3b,
    const int* __restrict__ iternum, float* __restrict__ out) {
    extern __shared__ char smem[];
    __half* pW1TD = (__half*)(smem + OFF_W1TD);
    __half* pW2TD = (__half*)(smem + OFF_W2TD);
    __half* pW2S  = (__half*)(smem + OFF_W2S);
    __half* pW3   = (__half*)(smem + OFF_W3);
    __half* pW1h  = (__half*)(smem + OFF_PW1);
    __half* pW2h  = (__half*)(smem + OFF_PW2);
    float*  pM1f  = (float*)(smem + OFF_PM1);
    __half* actAh = (__half*)(smem + OFF_ACTA);
    __half* actBh = (__half*)(smem + OFF_ACTB);
    __half* actCh = (__half*)(smem + OFF_ACTC);
    __half* actDh = (__half*)(smem + OFF_ACTD);
    float*  n0   = (float*)(smem + OFF_N0);
    float*  gbuf = (float*)(smem + OFF_GBUF);
    float*  zp2s = (float*)(smem + OFF_ZP2);
    float*  cb1s = (float*)(smem + OFF_CB1);
    __half* pV3h = (__half*)(smem + OFF_PV3);

    const int tid = threadIdx.x;
    const int cta = blockIdx.x;
    const int w = tid >> 5;
    const int lane = tid & 31;
    const int nj = (cta < H - 6 * NBLK) ? 7 : 6;

    const int jlw = w / 3, gatew = w % 3;
    const int j1 = cta + jlw * NBLK;
    const bool lstmw = (w < 21) && (jlw < nj);
    const int gofs = (gatew == 0) ? 0 : (gatew == 1) ? 2 * H : 3 * H;
    const int jl = w - 21;
    const int j7 = cta + jl * NBLK;
    const bool sevw = (w >= 21 && w < 28) && (jl < nj);
    const bool v1w = (w == 28) && (cta < C);
    const bool lossw = (cta == 0) && (w == 31);

    // striped-barrier per-slot constants (used by warps 0-7 lane 0)
    const unsigned ns_r = (w < 4) ? 19u : 18u;   // slots 0-3 own 19 CTAs, 4-7 own 18
    unsigned sbase_r = 0;
    if (w < 8 && lane == 0)
        asm volatile("ld.acquire.gpu.global.u32 %0, [%1];"
                     : "=r"(sbase_r) : "l"(g_sbase + w) : "memory");
    unsigned nbar = 0;

    // =================== phase 0: per-CTA convert + fuse (all local) ===================
    {
        __half* W0s = (__half*)smem;
        for (int i = tid; i < H * C; i += NT) W0s[i] = __float2half(W0w[i]);
        if (cta == 0) {
            for (int i = tid; i < H; i += NT) {
                g_TD1[i] = 0.f;
                g_r2[i] = 0.f; g_r3[i] = 0.f;
                g_s2[i] = 0.f; g_s3[i] = 0.f; g_BU2[i] = 0.f;
            }
            if (tid < 64) g_r1[tid] = 0.f;
        }
        __syncthreads();

        if (lstmw) {
            const float* wrow = Wih1 + (size_t)(gofs + j1) * (2 * H);
            float acc0 = 0.f, acc1 = 0.f, accb = 0.f;
            for (int k0 = 0; k0 < H; k0 += 32) {
                float wv = wrow[k0 + lane];
                accb += wv * W0b[k0 + lane];
#pragma unroll 8
                for (int kk = 0; kk < 32; ++kk) {
                    float ww = __shfl_sync(0xffffffffu, wv, kk);
                    int k = k0 + kk;
                    acc0 += ww * __half2float(W0s[k * C + lane]);
                    float w1v = (lane < C - 32) ? __half2float(W0s[k * C + lane + 32]) : 0.f;
                    acc1 += ww * w1v;
                }
            }
            pM1f[w * 64 + lane] = acc0;
            if (lane < C - 32) pM1f[w * 64 + lane + 32] = acc1;
            float cb = wred(accb);
            if (lane == 0) cb1s[w] = b1[gofs + j1] + cb;
        }
        __syncthreads();

        if (lstmw) {
            const float4* s1a = (const float4*)(Wih1 + (size_t)(gofs + j1) * (2 * H) + H);
            const float4* s2t = (const float4*)(Wih2 + (size_t)(gofs + j1) * (2 * H) + H);
            const float4* s2s = (const float4*)(Wih2 + (size_t)(gofs + j1) * (2 * H));
            const float4* s3a = (const float4*)(Wih3 + (size_t)(gofs + j1) * H);
            __half2* d1 = (__half2*)(pW1TD + w * 1024);
            __half2* d2 = (__half2*)(pW2TD + w * 1024);
            __half2* d3 = (__half2*)(pW2S  + w * 1024);
            __half2* d4 = (__half2*)(pW3   + w * 1024);
            for (int i = lane; i < 256; i += 32) {
                float4 v;
                v = __ldcg(s1a + i); d1[i*2] = __floats2half2_rn(v.x, v.y); d1[i*2+1] = __floats2half2_rn(v.z, v.w);
                v = __ldcg(s2t + i); d2[i*2] = __floats2half2_rn(v.x, v.y); d2[i*2+1] = __floats2half2_rn(v.z, v.w);
                v = __ldcg(s2s + i); d3[i*2] = __floats2half2_rn(v.x, v.y); d3[i*2+1] = __floats2half2_rn(v.z, v.w);
                v = __ldcg(s3a + i); d4[i*2] = __floats2half2_rn(v.x, v.y); d4[i*2+1] = __floats2half2_rn(v.z, v.w);
            }
        } else if (sevw) {
            const float4* sw1 = (const float4*)(W1w + (size_t)j7 * H);
            const float4* sw2 = (const float4*)(W2w + (size_t)j7 * H);
            const float4* sv3 = (const float4*)(V3w + (size_t)j7 * H);
            __half2* d1 = (__half2*)(pW1h + jl * 1024);
            __half2* d2 = (__half2*)(pW2h + jl * 1024);
            __half2* d3 = (__half2*)(pV3h + jl * 1024);
            for (int i = lane; i < 256; i += 32) {
                float4 v;
                v = __ldcg(sw1 + i); d1[i*2] = __floats2half2_rn(v.x, v.y); d1[i*2+1] = __floats2half2_rn(v.z, v.w);
                v = __ldcg(sw2 + i); d2[i*2] = __floats2half2_rn(v.x, v.y); d2[i*2+1] = __floats2half2_rn(v.z, v.w);
                v = __ldcg(sv3 + i); d3[i*2] = __floats2half2_rn(v.x, v.y); d3[i*2+1] = __floats2half2_rn(v.z, v.w);
            }
        }
        __syncthreads();
    }
    BAR_ARRIVE();
    BAR_WAIT();

    float r_cb1 = 0.f, r_b2 = 0.f, r_b3 = 0.f;
    float r_w1b = 0.f, r_w2b = 0.f, r_v2b = 0.f, r_v3b = 0.f, r_v1b = 0.f;
    if (lstmw) {
        r_cb1 = cb1s[w];
        r_b2  = b2[gofs + j1];
        r_b3  = b3[gofs + j1];
    }
    if (sevw) { r_w1b = W1b[j7]; r_w2b = W2b[j7]; r_v2b = V2b[j7]; r_v3b = V3b[j7]; }
    if (v1w) r_v1b = V1b[cta];

    float L0 = 0.f, L1 = 0.f, L2 = 0.f;

    for (int k = 0; k < T; ++k) {
        // ===== SP0: z1->s1(k) ; zp2 = Wih2td@nTD2(k-1)+b2 ;
        //            BU2 = W2@nTD2(k-1) ; r2 = V2@s2(k-1) ; loss0, loss2 =====
        {
            float aTD1 = __ldcg(&g_TD1[tid]);
            float s2v  = __ldcg(&g_s2[tid]);
            float r3v  = __ldcg(&g_r3[tid]);
            float ntd2 = s2v - r3v;
            actAh[tid] = __float2half(aTD1);
            actBh[tid] = __float2half(ntd2);
            actCh[tid] = __float2half(s2v);
            if (tid < 64)
                n0[tid] = (tid < C) ? (x[k * C + tid] - __ldcg(&g_r1[tid])) : 0.f;
            __syncthreads();
            if (lstmw) {
                float p = dotph(pW1TD + (size_t)w * 1024, actAh, lane);
                const float* m = pM1f + w * 64;
                p += m[lane] * n0[lane];
                if (lane < C - 32) p += m[lane + 32] * n0[lane + 32];
                float z1 = wred(p);
                float zp = wred(dotph(pW2TD + (size_t)w * 1024, actBh, lane));
                if (lane == 0) { gbuf[w] = z1 + r_cb1; zp2s[w] = zp + r_b2; }
            } else if (sevw && k > 0) {
                float bu  = wred(dotph(pW2h + (size_t)jl * 1024, actBh, lane));
                float r2n = wred(dotgh(V2w + (size_t)j7 * 1024, actCh, lane));
                if (lane == 0) {
                    __stcg(&g_BU2[j7], bu + r_w2b);
                    __stcg(&g_r2[j7], r2n + r_v2b);
                }
            } else if (lossw) {
                float v = fabsf(n0[lane]);
                if (lane < C - 32) v += fabsf(n0[lane + 32]);
                L0 += v;
                if (k > 0) {
                    float v2 = 0.f;
                    for (int m2 = lane; m2 < H; m2 += 32) v2 += fabsf(__half2float(actBh[m2]));
                    L2 += v2;
                }
            }
            __syncthreads();
            if (tid < nj) {
                float s = gatefn(gbuf[tid * 3], gbuf[tid * 3 + 1], gbuf[tid * 3 + 2]);
                __stcg(&g_s1[cta + tid * NBLK], s);
            }
            __syncthreads();
            BAR_ARRIVE();
            BAR_WAIT();
        }
        // ===== SP1: nTD1 = s1-r2 ; BU1 = W1@nTD1 ; r1 = V1@s1 ; loss1 ;
        //            z3 = Wih3@BU2 -> s3(k-1) =====
        {
            float bu2v = __ldcg(&g_BU2[tid]);
            float s1v  = __ldcg(&g_s1[tid]);
            float r2v  = __ldcg(&g_r2[tid]);
            float ntd1 = s1v - r2v;
            actBh[tid] = __float2half(bu2v);
            actCh[tid] = __float2half(ntd1);
            actDh[tid] = __float2half(s1v);
            if (cta == 0) __stcg(&g_TD1[tid], ntd1);
            __syncthreads();
            if (lstmw) {
                if (k > 0) {
                    float z3 = wred(dotph(pW3 + (size_t)w * 1024, actBh, lane));
                    if (lane == 0) gbuf[w] = z3 + r_b3;
                }
            } else if (sevw) {
                float bu = wred(dotph(pW1h + (size_t)jl * 1024, actCh, lane));
                if (lane == 0) __stcg(&g_BU1[j7], bu + r_w1b);
            } else if (v1w) {
                float r1n = wred(dotgh(V1w + (size_t)cta * 1024, actDh, lane));
                if (lane == 0) __stcg(&g_r1[cta], r1n + r_v1b);
            } else if (lossw) {
                float v = 0.f;
                for (int m2 = lane; m2 < H; m2 += 32) v += fabsf(__half2float(actCh[m2]));
                L1 += v;
            }
            __syncthreads();
            if (k > 0 && tid < nj) {
                float s = gatefn(gbuf[tid * 3], gbuf[tid * 3 + 1], gbuf[tid * 3 + 2]);
                __stcg(&g_s3[cta + tid * NBLK], s);
            }
            __syncthreads();
            BAR_ARRIVE();
            BAR_WAIT();
        }
        // ===== SP2: z2 = Wih2s@BU1 + zp2 -> s2(k) ; r3 = V3@s3(k-1) (smem V3) =====
        {
            actAh[tid] = __float2half(__ldcg(&g_BU1[tid]));
            actBh[tid] = __float2half(__ldcg(&g_s3[tid]));
            __syncthreads();
            if (lstmw) {
                float z2 = wred(dotph(pW2S + (size_t)w * 1024, actAh, lane));
                if (lane == 0) gbuf[w] = z2 + zp2s[w];
            } else if (sevw && k > 0) {
                float r3n = wred(dotph(pV3h + (size_t)jl * 1024, actBh, lane));
                if (lane == 0) __stcg(&g_r3[j7], r3n + r_v3b);
            }
            __syncthreads();
            if (tid < nj) {
                float s = gatefn(gbuf[tid * 3], gbuf[tid * 3 + 1], gbuf[tid * 3 + 2]);
                __stcg(&g_s2[cta + tid * NBLK], s);
            }
            __syncthreads();
            BAR_ARRIVE();
            BAR_WAIT();
        }
    }

    // pipeline drain: final loss2 term |nTD2(T-1)| = |s2(T-1) - V3@s3(T-2)|
    if (lossw) {
        float v = 0.f;
        for (int m2 = lane; m2 < H; m2 += 32)
            v += fabsf(__ldcg(&g_s2[m2]) - __ldcg(&g_r3[m2]));
        L2 += v;
        float l0 = wred(L0), l1 = wred(L1), l2 = wred(L2);
        if (lane == 0) {
            float lam = (iternum[0] <= 1000) ? 1e-4f : 1e-2f;
            out[0] = l0 + lam * l1 + lam * lam * l2;
        }
    }

    // advance per-slot bases for the next launch (stream-ordered; all arrivals
    // of this launch are complete once cta0 passes its final BAR_WAIT)
    if (cta == 0 && tid < NSLOT) {
        unsigned ov;
        asm volatile("ld.acquire.gpu.global.u32 %0, [%1];" : "=r"(ov) : "l"(g_sbase + tid) : "memory");
        unsigned nb = ov + (unsigned)NBAR_TOTAL * ((tid < 4) ? 19u : 18u);
        asm volatile("st.release.gpu.global.u32 [%0], %1;" :: "l"(g_sbase + tid), "r"(nb) : "memory");
    }
}

extern "C" void kernel_launch(void* const* d_in, const int* in_sizes, int n_in,
                              void* d_out, int out_size) {
    (void)in_sizes; (void)n_in; (void)out_size;
    const float* x    = (const float*)d_in[0];
    const float* W0w  = (const float*)d_in[1];
    const float* W0b  = (const float*)d_in[2];
    const float* W1w  = (const float*)d_in[3];
    const float* W1b  = (const float*)d_in[4];
    const float* W2w  = (const float*)d_in[5];
    const float* W2b  = (const float*)d_in[6];
    const float* Wih1 = (const float*)d_in[7];
    const float* b1   = (const float*)d_in[8];
    const float* Wih2 = (const float*)d_in[9];
    const float* b2   = (const float*)d_in[10];
    const float* Wih3 = (const float*)d_in[11];
    const float* b3   = (const float*)d_in[12];
    const float* V1w  = (const float*)d_in[13];
    const float* V1b  = (const float*)d_in[14];
    const float* V2w  = (const float*)d_in[15];
    const float* V2b  = (const float*)d_in[16];
    const float* V3w  = (const float*)d_in[17];
    const float* V3b  = (const float*)d_in[18];
    const int*   itn  = (const int*)d_in[19];

    static bool attr_set = false;
    if (!attr_set) {
        cudaFuncSetAttribute(predcells_kernel,
                             cudaFuncAttributeMaxDynamicSharedMemorySize, SMEM_BYTES);
        attr_set = true;
    }
    predcells_kernel<<<NBLK, NT, SMEM_BYTES>>>(
        x, W0w, W0b, W1w, W1b, W2w, W2b, Wih1, b1, Wih2, b2, Wih3, b3,
        V1w, V1b, V2w, V2b, V3w, V3b, itn, (float*)d_out);
}

// round 15
// speedup vs baseline: 1.4900x; 1.4900x over previous
#include <cuda_runtime.h>
#include <cuda_fp16.h>
#include <cstdint>

#define H 1024
#define C 56
#define T 64
#define NBLK 148
#define NT 1024

// ---------------- persistent global state (activations only) ----------------
__device__ __align__(16) float g_s1[H], g_s2[H], g_s3[H], g_BU1[H], g_BU2[H];
__device__ __align__(16) float g_TD1[H];
__device__ __align__(16) float g_r1[64], g_r2[H], g_r3[H];

// ---------------- monotonic-counter grid barrier, GPU-scope (R12/R13-proven) ----
// Single counter, single poller per CTA. (R14's 8-slot striped variant was a
// 45% regression: per-line poller count unchanged, 8x poll traffic, and
// release detection became a max over 8 slot-RTTs.)
__device__ unsigned g_cnt2;    // zero at load; grows monotonically forever
__device__ unsigned g_base;    // counter value at the start of this launch

#define NBAR_TOTAL (1 + 3 * T)

__device__ __forceinline__ float tanhx(float x) {
    float y;
    asm("tanh.approx.f32 %0, %1;" : "=f"(y) : "f"(x));
    return y;
}
__device__ __forceinline__ float gatefn(float zi, float zg, float zo) {
    float si = fmaf(0.5f, tanhx(0.5f * zi), 0.5f);
    float so = fmaf(0.5f, tanhx(0.5f * zo), 0.5f);
    return so * tanhx(si * tanhx(zg));
}

__device__ __forceinline__ float wred(float v) {
#pragma unroll
    for (int o = 16; o; o >>= 1) v += __shfl_xor_sync(0xffffffffu, v, o);
    return v;
}

// lane-partial dot: 1024 fp16 weights (smem) x 1024 fp16 acts (smem), fp32 accum
__device__ __forceinline__ float dotph(const __half* __restrict__ ws,
                                       const __half* __restrict__ as, int lane) {
    float acc = 0.f;
    int o = lane << 3;
#pragma unroll
    for (int it = 0; it < 4; ++it, o += 256) {
        uint4 u = *reinterpret_cast<const uint4*>(ws + o);
        uint4 a = *reinterpret_cast<const uint4*>(as + o);
        float2 w0 = __half22float2(*(__half2*)&u.x), b0 = __half22float2(*(__half2*)&a.x);
        float2 w1 = __half22float2(*(__half2*)&u.y), b1 = __half22float2(*(__half2*)&a.y);
        float2 w2 = __half22float2(*(__half2*)&u.z), b2 = __half22float2(*(__half2*)&a.z);
        float2 w3 = __half22float2(*(__half2*)&u.w), b3 = __half22float2(*(__half2*)&a.w);
        acc += w0.x * b0.x + w0.y * b0.y + w1.x * b1.x + w1.y * b1.y
             + w2.x * b2.x + w2.y * b2.y + w3.x * b3.x + w3.y * b3.y;
    }
    return acc;
}

// lane-partial dot: 1024 fp32 weights (GLOBAL via __ldcg) x 1024 fp16 acts (smem)
__device__ __forceinline__ float dotgh(const float* __restrict__ wg,
                                       const __half* __restrict__ as, int lane) {
    float acc = 0.f;
    int o = lane << 3;
#pragma unroll
    for (int it = 0; it < 4; ++it, o += 256) {
        float4 w0 = __ldcg(reinterpret_cast<const float4*>(wg + o));
        float4 w1 = __ldcg(reinterpret_cast<const float4*>(wg + o + 4));
        uint4 a = *reinterpret_cast<const uint4*>(as + o);
        float2 b0 = __half22float2(*(__half2*)&a.x);
        float2 b1 = __half22float2(*(__half2*)&a.y);
        float2 b2 = __half22float2(*(__half2*)&a.z);
        float2 b3 = __half22float2(*(__half2*)&a.w);
        acc += w0.x * b0.x + w0.y * b0.y + w0.z * b1.x + w0.w * b1.y
             + w1.x * b2.x + w1.y * b2.y + w1.z * b3.x + w1.w * b3.y;
    }
    return acc;
}

#define BAR_ARRIVE()                                                        \
    do {                                                                    \
        ++nbar;                                                             \
        if (tid == 0)                                                       \
            asm volatile("red.release.gpu.global.add.u32 [%0], %1;"         \
                         :: "l"(&g_cnt2), "r"(1u) : "memory");              \
    } while (0)

#define BAR_WAIT()                                                          \
    do {                                                                    \
        if (tid == 0) {                                                     \
            unsigned tgt = base + nbar * NBLK;                              \
            unsigned v;                                                     \
            do {                                                            \
                asm volatile("ld.acquire.gpu.global.u32 %0, [%1];"          \
                             : "=r"(v) : "l"(&g_cnt2) : "memory");          \
            } while ((int)(v - tgt) < 0);                                   \
        }                                                                   \
        __syncthreads();                                                    \
    } while (0)

// ---------------- smem layout (bytes) — weights RESIDENT ----------------
#define OFF_W1TD 0         // Wih1 TD half, 21 rows x 2048B fp16
#define OFF_W2TD 43008     // Wih2 TD half, 21 rows
#define OFF_W2S  86016     // Wih2 BU half, 21 rows
#define OFF_W3   129024    // Wih3, 21 rows
#define OFF_PW1  172032    // W1, 7 rows
#define OFF_PW2  186368    // W2, 7 rows
#define OFF_PM1  200704    // M1 = Wih1_bu @ W0, 21 rows x 64 fp32
#define OFF_ACTA 206080    // fp16 act buffers, 2048B each
#define OFF_ACTB 208128
#define OFF_ACTC 210176
#define OFF_ACTD 212224
#define OFF_N0   214272    // fp32, 256B
#define OFF_GBUF 214528
#define OFF_ZP2  214656
#define OFF_CB1  214784
#define OFF_PV3  214912    // V3, 7 rows x 2048B fp16 (r3 dot via LDS, not L2)
#define SMEM_BYTES 229248
// phase-0 W0 fp16 scratch (114,688 B at offset 0) overlaps the weight region;
// consumed (-> M1) before the weights are filled.

__global__ void __launch_bounds__(NT, 1) predcells_kernel(
    const float* __restrict__ x,
    const float* __restrict__ W0w, const float* __restrict__ W0b,
    const float* __restrict__ W1w, const float* __restrict__ W1b,
    const float* __restrict__ W2w, const float* __restrict__ W2b,
    const float* __restrict__ Wih1, const float* __restrict__ b1,
    const float* __restrict__ Wih2, const float* __restrict__ b2,
    const float* __restrict__ Wih3, const float* __restrict__ b3,
    const float* __restrict__ V1w, const float* __restrict__ V1b,
    const float* __restrict__ V2w, const float* __restrict__ V2b,
    const float* __restrict__ V3w, const float* __restrict__ V3b,
    const int* __restrict__ iternum, float* __restrict__ out) {
    extern __shared__ char smem[];
    __half* pW1TD = (__half*)(smem + OFF_W1TD);
    __half* pW2TD = (__half*)(smem + OFF_W2TD);
    __half* pW2S  = (__half*)(smem + OFF_W2S);
    __half* pW3   = (__half*)(smem + OFF_W3);
    __half* pW1h  = (__half*)(smem + OFF_PW1);
    __half* pW2h  = (__half*)(smem + OFF_PW2);
    float*  pM1f  = (float*)(smem + OFF_PM1);
    __half* actAh = (__half*)(smem + OFF_ACTA);
    __half* actBh = (__half*)(smem + OFF_ACTB);
    __half* actCh = (__half*)(smem + OFF_ACTC);
    __half* actDh = (__half*)(smem + OFF_ACTD);
    float*  n0   = (float*)(smem + OFF_N0);
    float*  gbuf = (float*)(smem + OFF_GBUF);
    float*  zp2s = (float*)(smem + OFF_ZP2);
    float*  cb1s = (float*)(smem + OFF_CB1);
    __half* pV3h = (__half*)(smem + OFF_PV3);

    const int tid = threadIdx.x;
    const int cta = blockIdx.x;
    const int w = tid >> 5;
    const int lane = tid & 31;
    const int nj = (cta < H - 6 * NBLK) ? 7 : 6;

    const int jlw = w / 3, gatew = w % 3;
    const int j1 = cta + jlw * NBLK;
    const bool lstmw = (w < 21) && (jlw < nj);
    const int gofs = (gatew == 0) ? 0 : (gatew == 1) ? 2 * H : 3 * H;
    const int jl = w - 21;
    const int j7 = cta + jl * NBLK;
    const bool sevw = (w >= 21 && w < 28) && (jl < nj);
    const bool v1w = (w == 28) && (cta < C);
    const bool lossw = (cta == 0) && (w == 31);

    unsigned base;
    asm volatile("ld.acquire.gpu.global.u32 %0, [%1];" : "=r"(base) : "l"(&g_base) : "memory");
    unsigned nbar = 0;

    // =================== phase 0: per-CTA convert + fuse (all local) ===================
    {
        __half* W0s = (__half*)smem;
        for (int i = tid; i < H * C; i += NT) W0s[i] = __float2half(W0w[i]);
        if (cta == 0) {
            for (int i = tid; i < H; i += NT) {
                g_TD1[i] = 0.f;
                g_r2[i] = 0.f; g_r3[i] = 0.f;
                g_s2[i] = 0.f; g_s3[i] = 0.f; g_BU2[i] = 0.f;
            }
            if (tid < 64) g_r1[tid] = 0.f;
        }
        __syncthreads();

        if (lstmw) {
            const float* wrow = Wih1 + (size_t)(gofs + j1) * (2 * H);
            float acc0 = 0.f, acc1 = 0.f, accb = 0.f;
            for (int k0 = 0; k0 < H; k0 += 32) {
                float wv = wrow[k0 + lane];
                accb += wv * W0b[k0 + lane];
#pragma unroll 8
                for (int kk = 0; kk < 32; ++kk) {
                    float ww = __shfl_sync(0xffffffffu, wv, kk);
                    int k = k0 + kk;
                    acc0 += ww * __half2float(W0s[k * C + lane]);
                    float w1v = (lane < C - 32) ? __half2float(W0s[k * C + lane + 32]) : 0.f;
                    acc1 += ww * w1v;
                }
            }
            pM1f[w * 64 + lane] = acc0;
            if (lane < C - 32) pM1f[w * 64 + lane + 32] = acc1;
            float cb = wred(accb);
            if (lane == 0) cb1s[w] = b1[gofs + j1] + cb;
        }
        __syncthreads();

        if (lstmw) {
            const float4* s1a = (const float4*)(Wih1 + (size_t)(gofs + j1) * (2 * H) + H);
            const float4* s2t = (const float4*)(Wih2 + (size_t)(gofs + j1) * (2 * H) + H);
            const float4* s2s = (const float4*)(Wih2 + (size_t)(gofs + j1) * (2 * H));
            const float4* s3a = (const float4*)(Wih3 + (size_t)(gofs + j1) * H);
            __half2* d1 = (__half2*)(pW1TD + w * 1024);
            __half2* d2 = (__half2*)(pW2TD + w * 1024);
            __half2* d3 = (__half2*)(pW2S  + w * 1024);
            __half2* d4 = (__half2*)(pW3   + w * 1024);
            for (int i = lane; i < 256; i += 32) {
                float4 v;
                v = __ldcg(s1a + i); d1[i*2] = __floats2half2_rn(v.x, v.y); d1[i*2+1] = __floats2half2_rn(v.z, v.w);
                v = __ldcg(s2t + i); d2[i*2] = __floats2half2_rn(v.x, v.y); d2[i*2+1] = __floats2half2_rn(v.z, v.w);
                v = __ldcg(s2s + i); d3[i*2] = __floats2half2_rn(v.x, v.y); d3[i*2+1] = __floats2half2_rn(v.z, v.w);
                v = __ldcg(s3a + i); d4[i*2] = __floats2half2_rn(v.x, v.y); d4[i*2+1] = __floats2half2_rn(v.z, v.w);
            }
        } else if (sevw) {
            const float4* sw1 = (const float4*)(W1w + (size_t)j7 * H);
            const float4* sw2 = (const float4*)(W2w + (size_t)j7 * H);
            const float4* sv3 = (const float4*)(V3w + (size_t)j7 * H);
            __half2* d1 = (__half2*)(pW1h + jl * 1024);
            __half2* d2 = (__half2*)(pW2h + jl * 1024);
            __half2* d3 = (__half2*)(pV3h + jl * 1024);
            for (int i = lane; i < 256; i += 32) {
                float4 v;
                v = __ldcg(sw1 + i); d1[i*2] = __floats2half2_rn(v.x, v.y); d1[i*2+1] = __floats2half2_rn(v.z, v.w);
                v = __ldcg(sw2 + i); d2[i*2] = __floats2half2_rn(v.x, v.y); d2[i*2+1] = __floats2half2_rn(v.z, v.w);
                v = __ldcg(sv3 + i); d3[i*2] = __floats2half2_rn(v.x, v.y); d3[i*2+1] = __floats2half2_rn(v.z, v.w);
            }
        }
        __syncthreads();
    }
    BAR_ARRIVE();
    BAR_WAIT();

    float r_cb1 = 0.f, r_b2 = 0.f, r_b3 = 0.f;
    float r_w1b = 0.f, r_w2b = 0.f, r_v2b = 0.f, r_v3b = 0.f, r_v1b = 0.f;
    if (lstmw) {
        r_cb1 = cb1s[w];
        r_b2  = b2[gofs + j1];
        r_b3  = b3[gofs + j1];
    }
    if (sevw) { r_w1b = W1b[j7]; r_w2b = W2b[j7]; r_v2b = V2b[j7]; r_v3b = V3b[j7]; }
    if (v1w) r_v1b = V1b[cta];

    float L0 = 0.f, L1 = 0.f, L2 = 0.f;

    for (int k = 0; k < T; ++k) {
        // ===== SP0: z1->s1(k) ; zp2 = Wih2td@nTD2(k-1)+b2 ;
        //            BU2 = W2@nTD2(k-1) ; r2 = V2@s2(k-1) ; loss0, loss2 =====
        {
            float aTD1 = __ldcg(&g_TD1[tid]);
            float s2v  = __ldcg(&g_s2[tid]);
            float r3v  = __ldcg(&g_r3[tid]);
            float ntd2 = s2v - r3v;
            actAh[tid] = __float2half(aTD1);
            actBh[tid] = __float2half(ntd2);
            actCh[tid] = __float2half(s2v);
            if (tid < 64)
                n0[tid] = (tid < C) ? (x[k * C + tid] - __ldcg(&g_r1[tid])) : 0.f;
            __syncthreads();
            if (lstmw) {
                float p = dotph(pW1TD + (size_t)w * 1024, actAh, lane);
                const float* m = pM1f + w * 64;
                p += m[lane] * n0[lane];
                if (lane < C - 32) p += m[lane + 32] * n0[lane + 32];
                float z1 = wred(p);
                float zp = wred(dotph(pW2TD + (size_t)w * 1024, actBh, lane));
                if (lane == 0) { gbuf[w] = z1 + r_cb1; zp2s[w] = zp + r_b2; }
            } else if (sevw && k > 0) {
                float bu  = wred(dotph(pW2h + (size_t)jl * 1024, actBh, lane));
                float r2n = wred(dotgh(V2w + (size_t)j7 * 1024, actCh, lane));
                if (lane == 0) {
                    __stcg(&g_BU2[j7], bu + r_w2b);
                    __stcg(&g_r2[j7], r2n + r_v2b);
                }
            } else if (lossw) {
                float v = fabsf(n0[lane]);
                if (lane < C - 32) v += fabsf(n0[lane + 32]);
                L0 += v;
                if (k > 0) {
                    float v2 = 0.f;
                    for (int m2 = lane; m2 < H; m2 += 32) v2 += fabsf(__half2float(actBh[m2]));
                    L2 += v2;
                }
            }
            __syncthreads();
            if (tid < nj) {
                float s = gatefn(gbuf[tid * 3], gbuf[tid * 3 + 1], gbuf[tid * 3 + 2]);
                __stcg(&g_s1[cta + tid * NBLK], s);
            }
            __syncthreads();
            BAR_ARRIVE();
            BAR_WAIT();
        }
        // ===== SP1: nTD1 = s1-r2 ; BU1 = W1@nTD1 ; r1 = V1@s1 ; loss1 ;
        //            z3 = Wih3@BU2 -> s3(k-1) =====
        {
            float bu2v = __ldcg(&g_BU2[tid]);
            float s1v  = __ldcg(&g_s1[tid]);
            float r2v  = __ldcg(&g_r2[tid]);
            float ntd1 = s1v - r2v;
            actBh[tid] = __float2half(bu2v);
            actCh[tid] = __float2half(ntd1);
            actDh[tid] = __float2half(s1v);
            if (cta == 0) __stcg(&g_TD1[tid], ntd1);
            __syncthreads();
            if (lstmw) {
                if (k > 0) {
                    float z3 = wred(dotph(pW3 + (size_t)w * 1024, actBh, lane));
                    if (lane == 0) gbuf[w] = z3 + r_b3;
                }
            } else if (sevw) {
                float bu = wred(dotph(pW1h + (size_t)jl * 1024, actCh, lane));
                if (lane == 0) __stcg(&g_BU1[j7], bu + r_w1b);
            } else if (v1w) {
                float r1n = wred(dotgh(V1w + (size_t)cta * 1024, actDh, lane));
                if (lane == 0) __stcg(&g_r1[cta], r1n + r_v1b);
            } else if (lossw) {
                float v = 0.f;
                for (int m2 = lane; m2 < H; m2 += 32) v += fabsf(__half2float(actCh[m2]));
                L1 += v;
            }
            __syncthreads();
            if (k > 0 && tid < nj) {
                float s = gatefn(gbuf[tid * 3], gbuf[tid * 3 + 1], gbuf[tid * 3 + 2]);
                __stcg(&g_s3[cta + tid * NBLK], s);
            }
            __syncthreads();
            BAR_ARRIVE();
            BAR_WAIT();
        }
        // ===== SP2: z2 = Wih2s@BU1 + zp2 -> s2(k) ; r3 = V3@s3(k-1) (smem V3) =====
        {
            actAh[tid] = __float2half(__ldcg(&g_BU1[tid]));
            actBh[tid] = __float2half(__ldcg(&g_s3[tid]));
            __syncthreads();
            if (lstmw) {
                float z2 = wred(dotph(pW2S + (size_t)w * 1024, actAh, lane));
                if (lane == 0) gbuf[w] = z2 + zp2s[w];
            } else if (sevw && k > 0) {
                float r3n = wred(dotph(pV3h + (size_t)jl * 1024, actBh, lane));
                if (lane == 0) __stcg(&g_r3[j7], r3n + r_v3b);
            }
            __syncthreads();
            if (tid < nj) {
                float s = gatefn(gbuf[tid * 3], gbuf[tid * 3 + 1], gbuf[tid * 3 + 2]);
                __stcg(&g_s2[cta + tid * NBLK], s);
            }
            __syncthreads();
            BAR_ARRIVE();
            BAR_WAIT();
        }
    }

    // pipeline drain: final loss2 term |nTD2(T-1)| = |s2(T-1) - V3@s3(T-2)|
    if (lossw) {
        float v = 0.f;
        for (int m2 = lane; m2 < H; m2 += 32)
            v += fabsf(__ldcg(&g_s2[m2]) - __ldcg(&g_r3[m2]));
        L2 += v;
        float l0 = wred(L0), l1 = wred(L1), l2 = wred(L2);
        if (lane == 0) {
            float lam = (iternum[0] <= 1000) ? 1e-4f : 1e-2f;
            out[0] = l0 + lam * l1 + lam * lam * l2;
        }
    }

    if (cta == 0 && tid == 0) {
        unsigned nb = base + (unsigned)NBAR_TOTAL * NBLK;
        asm volatile("st.release.gpu.global.u32 [%0], %1;" :: "l"(&g_base), "r"(nb) : "memory");
    }
}

extern "C" void kernel_launch(void* const* d_in, const int* in_sizes, int n_in,
                              void* d_out, int out_size) {
    (void)in_sizes; (void)n_in; (void)out_size;
    const float* x    = (const float*)d_in[0];
    const float* W0w  = (const float*)d_in[1];
    const float* W0b  = (const float*)d_in[2];
    const float* W1w  = (const float*)d_in[3];
    const float* W1b  = (const float*)d_in[4];
    const float* W2w  = (const float*)d_in[5];
    const float* W2b  = (const float*)d_in[6];
    const float* Wih1 = (const float*)d_in[7];
    const float* b1   = (const float*)d_in[8];
    const float* Wih2 = (const float*)d_in[9];
    const float* b2   = (const float*)d_in[10];
    const float* Wih3 = (const float*)d_in[11];
    const float* b3   = (const float*)d_in[12];
    const float* V1w  = (const float*)d_in[13];
    const float* V1b  = (const float*)d_in[14];
    const float* V2w  = (const float*)d_in[15];
    const float* V2b  = (const float*)d_in[16];
    const float* V3w  = (const float*)d_in[17];
    const float* V3b  = (const float*)d_in[18];
    const int*   itn  = (const int*)d_in[19];

    static bool attr_set = false;
    if (!attr_set) {
        cudaFuncSetAttribute(predcells_kernel,
                             cudaFuncAttributeMaxDynamicSharedMemorySize, SMEM_BYTES);
        attr_set = true;
    }
    predcells_kernel<<<NBLK, NT, SMEM_BYTES>>>(
        x, W0w, W0b, W1w, W1b, W2w, W2b, Wih1, b1, Wih2, b2, Wih3, b3,
        V1w, V1b, V2w, V2b, V3w, V3b, itn, (float*)d_out);
}